// round 1
// baseline (speedup 1.0000x reference)
#include <cuda_runtime.h>
#include <cstdint>

// MQIF neuron recurrence, sm_103a.
// input_current: [16, 4096, 512] f32
// outputs (flattened, concatenated): v_trace [16, 4097, 512] f32, spikes [16, 4097, 512] f32 (0/1)
//
// 8192 independent sequential chains (batch*features). Latency-bound design:
// 1 thread per neuron, 128 blocks x 64 threads (2 warps/SM on 128 SMs),
// double-buffered input prefetch (U=8), streaming loads/stores.

#define MQ_BATCH 16
#define MQ_STEPS 4096
#define MQ_FEAT  512
#define MQ_U     8   // steps per prefetch block

// constants
#define MQ_VR     (-60.0f)
#define MQ_VT     (-40.0f)
#define MQ_VRESET (-60.0f)
#define MQ_VPEAK  (30.0f)
#define MQ_A      (0.04f)
#define MQ_B      (0.2f)
#define MQ_D      (2.0f)
// dv = (...) / 10 -> * 0.1 ; du = (...) / 100 -> * 0.01 ; DT = 0.05

template <bool HAS_SPK>
__global__ __launch_bounds__(64, 1)
void mqif_kernel(const float* __restrict__ in,
                 float* __restrict__ vtr,
                 float* __restrict__ spk)
{
    const int idx = blockIdx.x * 64 + threadIdx.x;   // 0..8191
    const int b = idx >> 9;                          // /512
    const int f = idx & (MQ_FEAT - 1);

    const float* ip = in  + (size_t)b * MQ_STEPS       * MQ_FEAT + f;
    float*       vp = vtr + (size_t)b * (MQ_STEPS + 1) * MQ_FEAT + f;
    float*       sp = HAS_SPK ? (spk + (size_t)b * (MQ_STEPS + 1) * MQ_FEAT + f) : nullptr;

    float v = MQ_VR;   // v_init = vr
    float u = 0.0f;

    float bufA[MQ_U], bufB[MQ_U];

    // prime: load block 0
    #pragma unroll
    for (int k = 0; k < MQ_U; k++) bufA[k] = __ldcs(ip + k * MQ_FEAT);
    ip += MQ_U * MQ_FEAT;   // ip now points at block 1

    const int NBLK = MQ_STEPS / MQ_U;   // 512 (even)

    #define MQ_STEP(I_T)                                               \
    {                                                                  \
        const float i_t  = (I_T);                                      \
        const bool fired = (v >= MQ_VPEAK);                            \
        const float vvis = fired ? MQ_VPEAK : v;                       \
        __stcs(vp, vvis);  vp += MQ_FEAT;                              \
        if (HAS_SPK) { __stcs(sp, fired ? 1.0f : 0.0f); sp += MQ_FEAT; } \
        const float t0   = v - MQ_VR;          /* v + 60 */            \
        const float t1   = v - MQ_VT;          /* v + 40 */            \
        const float c    = MQ_A * t0;                                  \
        const float s    = fmaf(c, t1, i_t - u);  /* quad - u + i */   \
        const float dv   = s * 0.1f;                                   \
        const float du   = fmaf(MQ_B, t0, -u) * 0.01f;                 \
        const float vn   = fmaf(0.05f, dv, v);                         \
        const float un   = fmaf(0.05f, du, u);                         \
        v = fired ? MQ_VRESET  : vn;                                   \
        u = fired ? (u + MQ_D) : un;                                   \
    }

    for (int blk = 0; blk < NBLK; blk += 2) {
        // prefetch block blk+1 into bufB
        #pragma unroll
        for (int k = 0; k < MQ_U; k++) bufB[k] = __ldcs(ip + k * MQ_FEAT);

        // process bufA (block blk)
        #pragma unroll
        for (int k = 0; k < MQ_U; k++) MQ_STEP(bufA[k]);

        // prefetch block blk+2 into bufA (guarded)
        if (blk + 2 < NBLK) {
            #pragma unroll
            for (int k = 0; k < MQ_U; k++)
                bufA[k] = __ldcs(ip + (MQ_U + k) * MQ_FEAT);
        }

        // process bufB (block blk+1)
        #pragma unroll
        for (int k = 0; k < MQ_U; k++) MQ_STEP(bufB[k]);

        ip += 2 * MQ_U * MQ_FEAT;
    }

    // final entries at t = STEPS: raw v, spike = (v >= v_peak)
    __stcs(vp, v);
    if (HAS_SPK) __stcs(sp, (v >= MQ_VPEAK) ? 1.0f : 0.0f);

    #undef MQ_STEP
}

extern "C" void kernel_launch(void* const* d_in, const int* in_sizes, int n_in,
                              void* d_out, int out_size)
{
    const float* in = (const float*)d_in[0];
    float* out = (float*)d_out;

    const size_t total_v = (size_t)MQ_BATCH * (MQ_STEPS + 1) * MQ_FEAT;  // 33,562,624

    if ((size_t)out_size >= 2 * total_v) {
        // [v_trace | spikes] concatenated, both as f32
        mqif_kernel<true><<<128, 64>>>(in, out, out + total_v);
    } else {
        // v_trace only
        mqif_kernel<false><<<128, 64>>>(in, out, nullptr);
    }
}

// round 2
// speedup vs baseline: 1.9926x; 1.9926x over previous
#include <cuda_runtime.h>
#include <cstdint>

// MQIF neuron recurrence, sm_103a.
// input_current: [16, 4096, 512] f32
// outputs concatenated: v_trace [16,4097,512] f32, spikes [16,4097,512] f32
//
// Latency-bound sequential chains (8192 neurons x 4096 steps).
// 1 thread/neuron, 128 blocks x 64 threads (1 warp per SMSP on 2 SMSPs x 128 SMs).
// 4-buffer register ring (U=16) => prefetch distance ~3 blocks ~ 1000 cyc,
// hides DRAM latency. Recurrence in Horner form: 12-cyc arith chain.

#define MQ_BATCH 16
#define MQ_STEPS 4096
#define MQ_FEAT  512
#define MQ_U     16

#define MQ_VR     (-60.0f)
#define MQ_VPEAK  (30.0f)
#define MQ_VRESET (-60.0f)
#define MQ_D      (2.0f)

// v' = 2e-4 v^2 + 1.02 v + 0.48 + 0.005 i - 0.005 u   (no fire)
// u' = 0.9995 u + 1e-4 v + 6e-3                       (no fire)

template <bool HAS_SPK>
__global__ __launch_bounds__(64, 1)
void mqif_kernel(const float* __restrict__ in,
                 float* __restrict__ vtr,
                 float* __restrict__ spk)
{
    const int idx = blockIdx.x * 64 + threadIdx.x;   // 0..8191
    const int b = idx >> 9;
    const int f = idx & (MQ_FEAT - 1);

    const float* ip0 = in  + (size_t)b * MQ_STEPS       * MQ_FEAT + f;
    float*       vp  = vtr + (size_t)b * (MQ_STEPS + 1) * MQ_FEAT + f;
    float*       sp  = HAS_SPK ? (spk + (size_t)b * (MQ_STEPS + 1) * MQ_FEAT + f)
                               : nullptr;

    float v = MQ_VR;
    float u = 0.0f;

    float B0[MQ_U], B1[MQ_U], B2[MQ_U], B3[MQ_U];

    auto loadblk = [&](float* buf, int blki) {
        const float* bp = ip0 + (size_t)blki * MQ_U * MQ_FEAT;
        #pragma unroll
        for (int k = 0; k < MQ_U; k++) buf[k] = __ldcs(bp + k * MQ_FEAT);
    };

    auto process = [&](const float* buf) {
        #pragma unroll
        for (int k = 0; k < MQ_U; k++) {
            const float i_t   = buf[k];
            const bool  fired = (v >= MQ_VPEAK);
            __stcs(vp + k * MQ_FEAT, fminf(v, MQ_VPEAK));
            if (HAS_SPK) __stcs(sp + k * MQ_FEAT, fired ? 1.0f : 0.0f);
            const float p  = fmaf(-0.005f, u, 0.48f);
            const float h  = fmaf( 0.005f, i_t, p);
            const float g  = fmaf( 1.02f,  v, h);      // on v-chain
            const float w  = v * v;                    // on v-chain (parallel)
            const float vn = fmaf(2.0e-4f, w, g);      // on v-chain
            const float q  = fmaf(1.0e-4f, v, 6.0e-3f);
            const float un = fmaf(0.9995f, u, q);
            v = fired ? MQ_VRESET  : vn;               // FSEL closes chain
            u = fired ? (u + MQ_D) : un;
        }
        vp += MQ_U * MQ_FEAT;
        if (HAS_SPK) sp += MQ_U * MQ_FEAT;
    };

    const int NBLK = MQ_STEPS / MQ_U;   // 256, divisible by 4

    // prime pipeline: blocks 0,1,2 in flight
    loadblk(B0, 0);
    loadblk(B1, 1);
    loadblk(B2, 2);

    for (int blk = 0; blk < NBLK; blk += 4) {
        if (blk + 3 < NBLK) loadblk(B3, blk + 3);
        process(B0);
        if (blk + 4 < NBLK) loadblk(B0, blk + 4);
        process(B1);
        if (blk + 5 < NBLK) loadblk(B1, blk + 5);
        process(B2);
        if (blk + 6 < NBLK) loadblk(B2, blk + 6);
        process(B3);
    }

    // t = STEPS: raw final voltage, spike = (v >= v_peak)
    __stcs(vp, v);
    if (HAS_SPK) __stcs(sp, (v >= MQ_VPEAK) ? 1.0f : 0.0f);
}

extern "C" void kernel_launch(void* const* d_in, const int* in_sizes, int n_in,
                              void* d_out, int out_size)
{
    const float* in = (const float*)d_in[0];
    float* out = (float*)d_out;

    const size_t total_v = (size_t)MQ_BATCH * (MQ_STEPS + 1) * MQ_FEAT;

    if ((size_t)out_size >= 2 * total_v) {
        mqif_kernel<true><<<128, 64>>>(in, out, out + total_v);
    } else {
        mqif_kernel<false><<<128, 64>>>(in, out, nullptr);
    }
}

// round 3
// speedup vs baseline: 2.3074x; 1.1580x over previous
#include <cuda_runtime.h>
#include <cstdint>

// MQIF neuron recurrence, sm_103a.
// input_current: [16, 4096, 512] f32
// outputs concatenated: v_trace [16,4097,512] f32, spikes [16,4097,512] f32
//
// 8192 sequential chains, 1 thread/neuron, 128 blocks x 64 threads.
// 4-buffer register ring (U=16) hides DRAM latency (prefetch distance ~48 steps).
// Fire-handling is speculative: hot path has NO selects (v-chain = 8 cyc),
// spike stored as constant 0; a never-taken predicated fixup handles v>=v_peak
// exactly (vn=-60, un=u+2, spike re-stored as 1).

#define MQ_BATCH 16
#define MQ_STEPS 4096
#define MQ_FEAT  512
#define MQ_U     16

#define MQ_VPEAK  (30.0f)
#define MQ_VRESET (-60.0f)
#define MQ_D      (2.0f)

// no-fire update (expanded, Horner):
//   v' = 2e-4 v^2 + 1.02 v + 0.48 + 0.005 i - 0.005 u
//   u' = 0.9995 u + 1e-4 v + 6e-3

template <bool HAS_SPK>
__global__ __launch_bounds__(64, 1)
void mqif_kernel(const float* __restrict__ in,
                 float* __restrict__ vtr,
                 float* __restrict__ spk)
{
    const int idx = blockIdx.x * 64 + threadIdx.x;   // 0..8191
    const int b = idx >> 9;
    const int f = idx & (MQ_FEAT - 1);

    const float* ip0 = in  + (size_t)b * MQ_STEPS       * MQ_FEAT + f;
    float*       vp  = vtr + (size_t)b * (MQ_STEPS + 1) * MQ_FEAT + f;
    float*       sp  = HAS_SPK ? (spk + (size_t)b * (MQ_STEPS + 1) * MQ_FEAT + f)
                               : nullptr;

    float v = -60.0f;   // v_init = vr
    float u = 0.0f;

    float B0[MQ_U], B1[MQ_U], B2[MQ_U], B3[MQ_U];

    auto loadblk = [&](float* buf, int blki) {
        const float* bp = ip0 + (size_t)blki * MQ_U * MQ_FEAT;
        #pragma unroll
        for (int k = 0; k < MQ_U; k++) buf[k] = __ldcs(bp + k * MQ_FEAT);
    };

    auto process = [&](const float* buf) {
        #pragma unroll
        for (int k = 0; k < MQ_U; k++) {
            const float i_t = buf[k];

            // visible voltage: min handles the fired clamp exactly
            __stcs(vp + k * MQ_FEAT, fminf(v, MQ_VPEAK));
            if (HAS_SPK) __stcs(sp + k * MQ_FEAT, 0.0f);

            // speculative (no-fire) update — off the predicate path
            const float p  = fmaf(-0.005f, u, 0.48f);
            const float h  = fmaf( 0.005f, i_t, p);
            const float g  = fmaf( 1.02f,  v, h);
            const float w  = v * v;
            float vn = fmaf(2.0e-4f, w, g);
            float un = fmaf(0.9995f, u, fmaf(1.0e-4f, v, 6.0e-3f));

            // rare fixup: fire/reset semantics (never taken with this data,
            // but exact when taken)
            if (v >= MQ_VPEAK) {
                vn = MQ_VRESET;
                un = u + MQ_D;
                if (HAS_SPK) __stcs(sp + k * MQ_FEAT, 1.0f);
            }
            v = vn;
            u = un;
        }
        vp += MQ_U * MQ_FEAT;
        if (HAS_SPK) sp += MQ_U * MQ_FEAT;
    };

    const int NBLK = MQ_STEPS / MQ_U;   // 256, divisible by 4

    loadblk(B0, 0);
    loadblk(B1, 1);
    loadblk(B2, 2);

    for (int blk = 0; blk < NBLK; blk += 4) {
        if (blk + 3 < NBLK) loadblk(B3, blk + 3);
        process(B0);
        if (blk + 4 < NBLK) loadblk(B0, blk + 4);
        process(B1);
        if (blk + 5 < NBLK) loadblk(B1, blk + 5);
        process(B2);
        if (blk + 6 < NBLK) loadblk(B2, blk + 6);
        process(B3);
    }

    // t = STEPS: raw final voltage, spike = (v >= v_peak)
    __stcs(vp, v);
    if (HAS_SPK) __stcs(sp, (v >= MQ_VPEAK) ? 1.0f : 0.0f);
}

extern "C" void kernel_launch(void* const* d_in, const int* in_sizes, int n_in,
                              void* d_out, int out_size)
{
    const float* in = (const float*)d_in[0];
    float* out = (float*)d_out;

    const size_t total_v = (size_t)MQ_BATCH * (MQ_STEPS + 1) * MQ_FEAT;

    if ((size_t)out_size >= 2 * total_v) {
        mqif_kernel<true><<<128, 64>>>(in, out, out + total_v);
    } else {
        mqif_kernel<false><<<128, 64>>>(in, out, nullptr);
    }
}